// round 1
// baseline (speedup 1.0000x reference)
#include <cuda_runtime.h>

// Problem constants (fixed by the dataset)
#define N_NODES 20000
#define BATCH   16
#define PERIODS 12
#define EMAX    320000
#define FDIM    384          // BATCH * PERIODS * 2
#define BT      192          // BATCH * PERIODS

// ---------------- scratch (device globals: no allocation allowed) ----------
__device__ float g_Xfeat[(size_t)N_NODES * FDIM];   // packed [n][b][t][{val,mask}]
__device__ float g_agg  [(size_t)N_NODES * FDIM];   // GCN-aggregated features
__device__ float g_deg  [N_NODES];
__device__ float g_dinv [N_NODES];
__device__ int   g_count[N_NODES];
__device__ int   g_rowptr[N_NODES + 1];
__device__ int   g_cursor[N_NODES];
__device__ int   g_csrc [EMAX];
__device__ float g_cval [EMAX];
__device__ float g_gru  [84];   // [0:12) probs, Cz0, Cz1, cz, Ch0, Ch1, ch

__device__ __forceinline__ float tanh_fast(float x) {
    float y;
    asm("tanh.approx.f32 %0, %1;" : "=f"(y) : "f"(x));
    return y;
}

// ---------------- tiny constant-folding kernel -----------------------------
// Z = sigmoid(agg@Wz + bz) @ Lz_w[:12] + Lz_b  ==> affine in (a0, a1):
//   zarg_k = a0*Cz0[k] + a1*Cz1[k] + cz[k]     (H0 == 0 kills the rest)
__global__ void const_kernel(const float* __restrict__ Wz, const float* __restrict__ bz,
                             const float* __restrict__ Wh, const float* __restrict__ bh,
                             const float* __restrict__ Lzw, const float* __restrict__ Lzb,
                             const float* __restrict__ Lhw, const float* __restrict__ Lhb,
                             const float* __restrict__ att)
{
    int k = threadIdx.x;
    if (k >= PERIODS) return;
    float m = -1e30f;
    for (int t = 0; t < PERIODS; t++) m = fmaxf(m, att[t]);
    float s = 0.f;
    for (int t = 0; t < PERIODS; t++) s += expf(att[t] - m);
    g_gru[k] = expf(att[k] - m) / s;                    // softmax probs

    float c0 = 0.f, c1 = 0.f, cc = Lzb[k];
    float h0 = 0.f, h1 = 0.f, hc = Lhb[k];
    for (int p = 0; p < PERIODS; p++) {
        float lz = Lzw[p * PERIODS + k];
        float lh = Lhw[p * PERIODS + k];
        c0 += Wz[p] * lz;           c1 += Wz[PERIODS + p] * lz;  cc += bz[p] * lz;
        h0 += Wh[p] * lh;           h1 += Wh[PERIODS + p] * lh;  hc += bh[p] * lh;
    }
    g_gru[12 + k] = c0;  g_gru[24 + k] = c1;  g_gru[36 + k] = cc;
    g_gru[48 + k] = h0;  g_gru[60 + k] = h1;  g_gru[72 + k] = hc;
}

// ---------------- init ------------------------------------------------------
__global__ void init_kernel() {
    int n = blockIdx.x * blockDim.x + threadIdx.x;
    if (n < N_NODES) { g_deg[n] = 1.0f; g_count[n] = 0; }   // self-loop weight 1
}

// ---------------- pack: [B,P,N] x/mask/noise -> Xfeat[n][b][t][{v,m}] ------
// smem-tiled transpose: 16 nodes per 256-thread block, fully coalesced out.
__global__ void pack_kernel(const float* __restrict__ x,
                            const float* __restrict__ mask,
                            const float* __restrict__ noise)
{
    __shared__ float sval[BT * 17];
    __shared__ float smsk[BT * 17];
    int tid = threadIdx.x;
    int n0  = blockIdx.x * 16;

    for (int i = tid; i < BT * 16; i += 256) {
        int bt = i >> 4, nl = i & 15;
        int g  = bt * N_NODES + n0 + nl;
        float mv = mask[g];
        float fv = fmaf(mv, x[g], (1.0f - mv) * noise[g]);  // GAIN fill
        sval[bt * 17 + nl] = fv;
        smsk[bt * 17 + nl] = mv;
    }
    __syncthreads();
    for (int i = tid; i < 16 * FDIM; i += 256) {
        int nl = i / FDIM;
        int f  = i - nl * FDIM;
        int bt = f >> 1;
        float v = (f & 1) ? smsk[bt * 17 + nl] : sval[bt * 17 + nl];
        g_Xfeat[(size_t)(n0 + nl) * FDIM + f] = v;
    }
}

// ---------------- degree histogram ------------------------------------------
__global__ void deg_kernel(const int* __restrict__ dst, const float* __restrict__ w, int E) {
    int e = blockIdx.x * blockDim.x + threadIdx.x;
    if (e < E) {
        int d = dst[e];
        atomicAdd(&g_deg[d], w[e]);
        atomicAdd(&g_count[d], 1);
    }
}

__global__ void dinv_kernel() {
    int n = blockIdx.x * blockDim.x + threadIdx.x;
    if (n < N_NODES) g_dinv[n] = rsqrtf(g_deg[n]);   // deg >= 1 always
}

// ---------------- single-block exclusive scan for rowptr --------------------
__global__ void scan_kernel() {
    __shared__ int part[1024];
    const int CH = 20;                    // 1024*20 >= 20000
    int tid  = threadIdx.x;
    int base = tid * CH;
    int s = 0;
    for (int j = 0; j < CH; j++) {
        int idx = base + j;
        if (idx < N_NODES) s += g_count[idx];
    }
    part[tid] = s;
    __syncthreads();
    for (int off = 1; off < 1024; off <<= 1) {
        int v = (tid >= off) ? part[tid - off] : 0;
        __syncthreads();
        part[tid] += v;
        __syncthreads();
    }
    int run = (tid == 0) ? 0 : part[tid - 1];
    for (int j = 0; j < CH; j++) {
        int idx = base + j;
        if (idx < N_NODES) {
            g_rowptr[idx] = run;
            g_cursor[idx] = run;
            run += g_count[idx];
        }
    }
    if (tid == 1023) g_rowptr[N_NODES] = part[1023];
}

// ---------------- CSR placement ---------------------------------------------
__global__ void place_kernel(const int* __restrict__ src, const int* __restrict__ dst,
                             const float* __restrict__ w, int E) {
    int e = blockIdx.x * blockDim.x + threadIdx.x;
    if (e < E) {
        int d = dst[e];
        int s = src[e];
        int pos = atomicAdd(&g_cursor[d], 1);
        g_csrc[pos] = s;
        g_cval[pos] = g_dinv[s] * w[e];   // dinv[dst] factored out below
    }
}

// ---------------- gather SpMM: agg = D^-1/2 A D^-1/2 @ Xfeat ----------------
// one block (128 threads) per destination node; 3 floats per thread.
__global__ void __launch_bounds__(128) spmm_kernel() {
    int n   = blockIdx.x;
    int tid = threadIdx.x;
    float di = g_dinv[n];
    const float* __restrict__ xn = g_Xfeat + (size_t)n * FDIM;
    float acc0 = di * xn[tid];          // self-loop: dinv[n]*X[n]
    float acc1 = di * xn[tid + 128];
    float acc2 = di * xn[tid + 256];
    int e  = g_rowptr[n];
    int e1 = g_rowptr[n + 1];
    for (; e < e1; e++) {
        int   s = g_csrc[e];
        float w = g_cval[e];
        const float* __restrict__ xs = g_Xfeat + (size_t)s * FDIM;
        acc0 = fmaf(w, xs[tid],       acc0);
        acc1 = fmaf(w, xs[tid + 128], acc1);
        acc2 = fmaf(w, xs[tid + 256], acc2);
    }
    float* an = g_agg + (size_t)n * FDIM;
    an[tid]       = di * acc0;
    an[tid + 128] = di * acc1;
    an[tid + 256] = di * acc2;
}

// ---------------- fused GRU-scan + MLP head + output ------------------------
__global__ void __launch_bounds__(256) gru_kernel(
    const float* __restrict__ x, const float* __restrict__ mask,
    const float* __restrict__ W1, const float* __restrict__ b1,
    const float* __restrict__ W2, const float* __restrict__ b2,
    float* __restrict__ res, float* __restrict__ imp)
{
    __shared__ float sC[84], sW1[144], sW2[144], sb1[12], sb2[12];
    int tid = threadIdx.x;
    if (tid < 84)  sC[tid]  = g_gru[tid];
    if (tid < 144) { sW1[tid] = W1[tid]; sW2[tid] = W2[tid]; }
    if (tid < 12)  { sb1[tid] = b1[tid]; sb2[tid] = b2[tid]; }
    __syncthreads();

    int gid = blockIdx.x * 256 + tid;
    int b = gid / N_NODES;
    int n = gid - b * N_NODES;

    // 24 floats: (a0,a1) for t = 0..11 of this (b,n)
    const float4* ap = reinterpret_cast<const float4*>(g_agg + (size_t)n * FDIM + b * 24);
    float a[24];
#pragma unroll
    for (int i = 0; i < 6; i++) {
        float4 v = ap[i];
        a[4*i] = v.x; a[4*i+1] = v.y; a[4*i+2] = v.z; a[4*i+3] = v.w;
    }
    float probs[12];
#pragma unroll
    for (int t = 0; t < 12; t++) probs[t] = sC[t];

    float acc[12];
#pragma unroll
    for (int k = 0; k < 12; k++) {
        float cz0 = sC[12+k], cz1 = sC[24+k], czc = sC[36+k];
        float ch0 = sC[48+k], ch1 = sC[60+k], chc = sC[72+k];
        float s = 0.f;
#pragma unroll
        for (int t = 0; t < 12; t++) {
            float a0 = a[2*t], a1 = a[2*t+1];
            float zarg = fmaf(a0, cz0, fmaf(a1, cz1, czc));
            float harg = fmaf(a0, ch0, fmaf(a1, ch1, chc));
            // (1 - sigmoid(z)) = 0.5 - 0.5*tanh(z/2)
            float oneMz = fmaf(-0.5f, tanh_fast(0.5f * zarg), 0.5f);
            s = fmaf(probs[t] * oneMz, tanh_fast(harg), s);
        }
        acc[k] = fmaxf(s, 0.f);          // relu(H_accum)
    }

    float h1[12];
#pragma unroll
    for (int k = 0; k < 12; k++) {
        float v = sb1[k];
#pragma unroll
        for (int j = 0; j < 12; j++) v = fmaf(acc[j], sW1[j*12 + k], v);
        h1[k] = fmaxf(v, 0.f);
    }

    size_t obase = (size_t)b * (PERIODS * N_NODES) + n;
#pragma unroll
    for (int k = 0; k < 12; k++) {
        float v = sb2[k];
#pragma unroll
        for (int j = 0; j < 12; j++) v = fmaf(h1[j], sW2[j*12 + k], v);
        float im = fmaf(0.5f, tanh_fast(0.5f * v), 0.5f);   // sigmoid
        size_t idx = obase + (size_t)k * N_NODES;
        float mv = mask[idx];
        res[idx] = fmaf(mv, x[idx], (1.0f - mv) * im);      // mask in {0,1}
        if (imp) imp[idx] = im;
    }
}

// ---------------- launcher ---------------------------------------------------
extern "C" void kernel_launch(void* const* d_in, const int* in_sizes, int n_in,
                              void* d_out, int out_size)
{
    const float* x     = (const float*)d_in[0];
    const float* mask  = (const float*)d_in[1];
    const float* noise = (const float*)d_in[2];
    const int*   ei    = (const int*)  d_in[3];
    const float* ew    = (const float*)d_in[4];
    const float* Wz  = (const float*)d_in[5];
    const float* bz  = (const float*)d_in[6];
    // d_in[7], d_in[8]  (Wr, br)   : dead — H0*R == 0
    const float* Wh  = (const float*)d_in[9];
    const float* bh  = (const float*)d_in[10];
    const float* Lzw = (const float*)d_in[11];
    const float* Lzb = (const float*)d_in[12];
    // d_in[13], d_in[14] (Lr_w, Lr_b): dead
    const float* Lhw = (const float*)d_in[15];
    const float* Lhb = (const float*)d_in[16];
    const float* att = (const float*)d_in[17];
    const float* W1  = (const float*)d_in[18];
    const float* b1  = (const float*)d_in[19];
    const float* W2  = (const float*)d_in[20];
    const float* b2  = (const float*)d_in[21];

    int E = in_sizes[4];                       // 320000
    const int* src = ei;
    const int* dst = ei + E;

    const size_t OUT_HALF = (size_t)BATCH * PERIODS * N_NODES;
    float* res = (float*)d_out;
    float* imp = ((size_t)out_size >= 2 * OUT_HALF) ? res + OUT_HALF : nullptr;

    const_kernel<<<1, 32>>>(Wz, bz, Wh, bh, Lzw, Lzb, Lhw, Lhb, att);
    init_kernel<<<(N_NODES + 255) / 256, 256>>>();
    pack_kernel<<<N_NODES / 16, 256>>>(x, mask, noise);
    deg_kernel<<<(E + 255) / 256, 256>>>(dst, ew, E);
    dinv_kernel<<<(N_NODES + 255) / 256, 256>>>();
    scan_kernel<<<1, 1024>>>();
    place_kernel<<<(E + 255) / 256, 256>>>(src, dst, ew, E);
    spmm_kernel<<<N_NODES, 128>>>();
    gru_kernel<<<(BATCH * N_NODES) / 256, 256>>>(x, mask, W1, b1, W2, b2, res, imp);
}